// round 12
// baseline (speedup 1.0000x reference)
#include <cuda_runtime.h>
#include <cuda_fp16.h>

#define FLAT 12288
#define HID  4096
#define NS   16
#define KST  4
#define LRf  0.01f
#define RCH  96          // row chunks for W^T v partials (128 rows each)
#define ROWS_PER_CH 128
#define CTH  1024        // cheap-phase threads (single block)
#define VPT  (FLAT / CTH)   // 12 v-elements per thread
#define HPT  (HID / CTH)    // 4 h-elements per thread

// ---------------- device scratch (static, no runtime allocation) ----------------
__device__ __half g_Wh[(size_t)FLAT * HID];  // fp16 copy of W (96 MB)
__device__ float g_part[RCH * HID];   // gemvT partial column sums
__device__ float g_h[HID];            // dense-phase working h
__device__ float g_hA[HID];           // hinit_0 (q)
__device__ float g_hB[HID];           // hfinal_0 (s)
__device__ float g_vA[FLAT];          // vfinal_0 (r)

__device__ __forceinline__ float sigm(float x) { return 1.f / (1.f + __expf(-x)); }

// ---------------- dense phase: sample 0 (proven R10 config) ----------------

// Pass 1 of gemvT, fused with W->fp16 conversion: reads fp32 W (200MB) once,
// emits fp16 copy (100MB) and partial column sums. 128-row chunks, grid (8,96).
__global__ void k_gemvT_conv(const float* __restrict__ W, const float* __restrict__ v) {
    __shared__ float sv[ROWS_PER_CH];
    int r0 = blockIdx.y * ROWS_PER_CH;
    if (threadIdx.x < ROWS_PER_CH) sv[threadIdx.x] = v[r0 + threadIdx.x];
    __syncthreads();
    int col2 = blockIdx.x * 256 + threadIdx.x;      // float2/half2 column index
    const float2* Wp = (const float2*)W + (size_t)r0 * (HID / 2) + col2;
    __half2* Whp = (__half2*)g_Wh + (size_t)r0 * (HID / 2) + col2;
    float ax = 0.f, ay = 0.f;
#pragma unroll 8
    for (int r = 0; r < ROWS_PER_CH; r++) {
        float2 w = Wp[(size_t)r * (HID / 2)];
        Whp[(size_t)r * (HID / 2)] = __floats2half2_rn(w.x, w.y);
        float s = sv[r];
        ax += w.x * s;
        ay += w.y * s;
    }
    float2 o; o.x = ax; o.y = ay;
    ((float2*)g_part)[blockIdx.y * (HID / 2) + col2] = o;
}

// Passes 2..4: fp16 W. 256 threads x half2 (512 cols per block), grid (8, 96).
__global__ void k_gemvT(const float* __restrict__ v) {
    __shared__ float sv[ROWS_PER_CH];
    int r0 = blockIdx.y * ROWS_PER_CH;
    if (threadIdx.x < ROWS_PER_CH) sv[threadIdx.x] = v[r0 + threadIdx.x];
    __syncthreads();
    int col2 = blockIdx.x * 256 + threadIdx.x;      // half2 column index
    const __half2* Wp = (const __half2*)g_Wh + (size_t)r0 * (HID / 2) + col2;
    float ax = 0.f, ay = 0.f;
#pragma unroll 8
    for (int r = 0; r < ROWS_PER_CH; r++) {
        float2 w = __half22float2(Wp[(size_t)r * (HID / 2)]);
        float s = sv[r];
        ax += w.x * s;
        ay += w.y * s;
    }
    float2 o; o.x = ax; o.y = ay;
    ((float2*)g_part)[blockIdx.y * (HID / 2) + col2] = o;
}

// reduce partials + bias + sigmoid -> g_h; optionally save hinit/hfinal
__global__ void k_hred(const float* __restrict__ b, int save) {
    int j = blockIdx.x * 256 + threadIdx.x;
    float s = b[j];
#pragma unroll 8
    for (int r = 0; r < RCH; r++) s += g_part[r * HID + j];
    float h = sigm(s);
    g_h[j] = h;
    if (save == 1) g_hA[j] = h;        // hinit_0 (q for sample 1)
    else if (save == 2) g_hB[j] = h;   // hfinal_0 (s for sample 1)
}

// v = sigmoid(a + W h): one warp per row, 16 rows per 512-thread block, uint4 loads.
__global__ void k_gemv(const float* __restrict__ a) {
    __shared__ float sh[HID];
    for (int k = threadIdx.x; k < HID; k += blockDim.x) sh[k] = g_h[k];
    __syncthreads();
    int warp = threadIdx.x >> 5, lane = threadIdx.x & 31;
    int row = blockIdx.x * 16 + warp;
    const uint4* Wr = (const uint4*)(g_Wh + (size_t)row * HID);   // 8 halves/load
    float acc = 0.f;
#pragma unroll 8
    for (int i = lane; i < HID / 8; i += 32) {
        uint4 wv = Wr[i];
        float2 f0 = __half22float2(*reinterpret_cast<__half2*>(&wv.x));
        float2 f1 = __half22float2(*reinterpret_cast<__half2*>(&wv.y));
        float2 f2 = __half22float2(*reinterpret_cast<__half2*>(&wv.z));
        float2 f3 = __half22float2(*reinterpret_cast<__half2*>(&wv.w));
        float4 h0 = *(const float4*)&sh[8 * i];
        float4 h1 = *(const float4*)&sh[8 * i + 4];
        acc += f0.x * h0.x + f0.y * h0.y + f1.x * h0.z + f1.y * h0.w;
        acc += f2.x * h1.x + f2.y * h1.y + f3.x * h1.z + f3.y * h1.w;
    }
#pragma unroll
    for (int o = 16; o; o >>= 1) acc += __shfl_down_sync(0xffffffffu, acc, o);
    if (lane == 0) g_vA[row] = sigm(a[row] + acc);
}

// ---------------- cheap phase: samples 1..15, rank-2 W, register-resident ----------
// Fixed thread->element mapping: every thread re-reads only elements it wrote,
// so the whole carry state (q,s,r) lives in REGISTERS. Only `inputs` is loaded
// (L2-hot) and `out` stored. Per phase: register math + one block reduction.

__device__ __forceinline__ float2 blockdot2(float a, float b) {
    __shared__ float ra[32], rb[32], bc[2];
#pragma unroll
    for (int o = 16; o; o >>= 1) {
        a += __shfl_down_sync(0xffffffffu, a, o);
        b += __shfl_down_sync(0xffffffffu, b, o);
    }
    int w = threadIdx.x >> 5;
    if ((threadIdx.x & 31) == 0) { ra[w] = a; rb[w] = b; }
    __syncthreads();
    if (threadIdx.x < 32) {
        float x = ra[threadIdx.x], y = rb[threadIdx.x];
#pragma unroll
        for (int o = 16; o; o >>= 1) {
            x += __shfl_down_sync(0xffffffffu, x, o);
            y += __shfl_down_sync(0xffffffffu, y, o);
        }
        if (threadIdx.x == 0) { bc[0] = x; bc[1] = y; }
    }
    __syncthreads();
    float2 r; r.x = bc[0]; r.y = bc[1];
    return r;
}

__global__ void __launch_bounds__(CTH, 1) k_cheap(const float* __restrict__ inp,
                                                  float* __restrict__ out) {
    const int tid = threadIdx.x;
    float rq[HPT], rs[HPT], rqn[HPT], rsn[HPT], rr[VPT], rp[VPT];

    // load carry state into registers (each thread only its own elements)
#pragma unroll
    for (int jj = 0; jj < HPT; jj++) {
        rq[jj] = g_hA[tid + jj * CTH];
        rs[jj] = g_hB[tid + jj * CTH];
    }
#pragma unroll
    for (int kk = 0; kk < VPT; kk++) rr[kk] = g_vA[tid + kk * CTH];

    // entry dots: d1 = inputs[0].inputs[1], d2 = vfinal_0.inputs[1]
    float2 dv;
    {
        float a1 = 0.f, a2 = 0.f;
#pragma unroll
        for (int kk = 0; kk < VPT; kk++) {
            int k = tid + kk * CTH;
            float x1v = inp[FLAT + k];
            a1 += inp[k] * x1v;
            a2 += rr[kk] * x1v;
        }
        dv = blockdot2(a1, a2);
    }

    for (int i = 1; i < NS; i++) {
        const float* p  = inp + (size_t)(i - 1) * FLAT;   // v_init of prev sample
        const float* pn = inp + (size_t)i * FLAT;         // v_init of this sample
        const float* xn = pn + FLAT;                      // next v_init (guarded)
#pragma unroll
        for (int kk = 0; kk < VPT; kk++) rp[kk] = p[tid + kk * CTH];

        for (int t = 1; t <= KST; t++) {
            // ---- h phase: h = sigm(LR*(q*(1+d1) - s*(1+d2))); dots q.h, s.h
            float c1 = 1.f + dv.x, c2 = 1.f + dv.y;
            float a3 = 0.f, a4 = 0.f;
#pragma unroll
            for (int jj = 0; jj < HPT; jj++) {
                float h = sigm(LRf * (rq[jj] * c1 - rs[jj] * c2));
                if (t == 1) rqn[jj] = h;
                if (t == KST) rsn[jj] = h;
                a3 += rq[jj] * h;
                a4 += rs[jj] * h;
            }
            float2 dh = blockdot2(a3, a4);

            // ---- v phase: v = sigm(LR*(p*(1+d3) - r*(1+d4))); next-step dots
            float c3 = 1.f + dh.x, c4 = 1.f + dh.y;
            float a1 = 0.f, a2 = 0.f;
            if (t < KST) {
#pragma unroll
                for (int kk = 0; kk < VPT; kk++) {
                    float v = sigm(LRf * (rp[kk] * c3 - rr[kk] * c4));
                    a1 += rp[kk] * v;      // p.v for next step
                    a2 += rr[kk] * v;      // r.v for next step
                }
            } else if (i < NS - 1) {
#pragma unroll
                for (int kk = 0; kk < VPT; kk++) {
                    int k = tid + kk * CTH;
                    float v = sigm(LRf * (rp[kk] * c3 - rr[kk] * c4));
                    rr[kk] = v;                        // vfinal_i -> r (register)
                    float xnk = xn[k];
                    a1 += pn[k] * xnk;                 // inputs[i].inputs[i+1]
                    a2 += v * xnk;                     // vfinal_i.inputs[i+1]
                }
            } else {
#pragma unroll
                for (int kk = 0; kk < VPT; kk++) {
                    int k = tid + kk * CTH;
                    float v = sigm(LRf * (rp[kk] * c3 - rr[kk] * c4));
                    out[k] = v;                        // final reconstruction
                }
            }
            dv = blockdot2(a1, a2);
        }
        // carry rotate: pure register copies
#pragma unroll
        for (int jj = 0; jj < HPT; jj++) { rq[jj] = rqn[jj]; rs[jj] = rsn[jj]; }
    }
}

// ---------------- launch ----------------

extern "C" void kernel_launch(void* const* d_in, const int* in_sizes, int n_in,
                              void* d_out, int out_size) {
    const float* inp = (const float*)d_in[0];  // (16, 64, 64, 3) = 16 x 12288
    const float* W   = (const float*)d_in[1];  // (12288, 4096)
    const float* a   = (const float*)d_in[2];  // (12288, 1)
    const float* b   = (const float*)d_in[3];  // (4096, 1)
    float* out = (float*)d_out;                // (12288, 1)

    float* vA = 0;
    cudaGetSymbolAddress((void**)&vA, g_vA);

    dim3 gT(HID / 512, RCH);
    for (int s = 0; s < KST; s++) {
        if (s == 0) k_gemvT_conv<<<gT, 256>>>(W, inp);   // fused fp16 conversion
        else        k_gemvT<<<gT, 256>>>(vA);
        k_hred<<<HID / 256, 256>>>(b, (s == 0) ? 1 : ((s == KST - 1) ? 2 : 0));
        k_gemv<<<FLAT / 16, 512>>>(a);
    }
    k_cheap<<<1, CTH>>>(inp, out);
}

// round 13
// speedup vs baseline: 1.4022x; 1.4022x over previous
#include <cuda_runtime.h>
#include <cuda_fp16.h>

#define FLAT 12288
#define HID  4096
#define NS   16
#define KST  4
#define LRf  0.01f
#define RCH  96          // row chunks for W^T v partials (128 rows each)
#define ROWS_PER_CH 128
#define CTH  1024        // cheap-phase threads (single block)
#define VPT  (FLAT / CTH)   // 12 v-elements per thread
#define HPT  (HID / CTH)    // 4 h-elements per thread

// ---------------- device scratch (static, no runtime allocation) ----------------
__device__ __half g_Wh[(size_t)FLAT * HID];  // fp16 copy of W (96 MB)
__device__ float g_part[RCH * HID];   // gemvT partial column sums
__device__ float g_h[HID];            // dense-phase working h
__device__ float g_hA[HID];           // hinit_0 (q)
__device__ float g_hB[HID];           // hfinal_0 (s)
__device__ float g_vA[FLAT];          // vfinal_0 (r)

__device__ __forceinline__ float sigm(float x) { return 1.f / (1.f + __expf(-x)); }

// ---------------- dense phase: sample 0 (proven R10 config, untouched) ----------------

// Pass 1 of gemvT, fused with W->fp16 conversion: reads fp32 W (200MB) once,
// emits fp16 copy (100MB) and partial column sums. 128-row chunks, grid (8,96).
__global__ void k_gemvT_conv(const float* __restrict__ W, const float* __restrict__ v) {
    __shared__ float sv[ROWS_PER_CH];
    int r0 = blockIdx.y * ROWS_PER_CH;
    if (threadIdx.x < ROWS_PER_CH) sv[threadIdx.x] = v[r0 + threadIdx.x];
    __syncthreads();
    int col2 = blockIdx.x * 256 + threadIdx.x;      // float2/half2 column index
    const float2* Wp = (const float2*)W + (size_t)r0 * (HID / 2) + col2;
    __half2* Whp = (__half2*)g_Wh + (size_t)r0 * (HID / 2) + col2;
    float ax = 0.f, ay = 0.f;
#pragma unroll 8
    for (int r = 0; r < ROWS_PER_CH; r++) {
        float2 w = Wp[(size_t)r * (HID / 2)];
        Whp[(size_t)r * (HID / 2)] = __floats2half2_rn(w.x, w.y);
        float s = sv[r];
        ax += w.x * s;
        ay += w.y * s;
    }
    float2 o; o.x = ax; o.y = ay;
    ((float2*)g_part)[blockIdx.y * (HID / 2) + col2] = o;
}

// Passes 2..4: fp16 W. 256 threads x half2 (512 cols per block), grid (8, 96).
__global__ void k_gemvT(const float* __restrict__ v) {
    __shared__ float sv[ROWS_PER_CH];
    int r0 = blockIdx.y * ROWS_PER_CH;
    if (threadIdx.x < ROWS_PER_CH) sv[threadIdx.x] = v[r0 + threadIdx.x];
    __syncthreads();
    int col2 = blockIdx.x * 256 + threadIdx.x;      // half2 column index
    const __half2* Wp = (const __half2*)g_Wh + (size_t)r0 * (HID / 2) + col2;
    float ax = 0.f, ay = 0.f;
#pragma unroll 8
    for (int r = 0; r < ROWS_PER_CH; r++) {
        float2 w = __half22float2(Wp[(size_t)r * (HID / 2)]);
        float s = sv[r];
        ax += w.x * s;
        ay += w.y * s;
    }
    float2 o; o.x = ax; o.y = ay;
    ((float2*)g_part)[blockIdx.y * (HID / 2) + col2] = o;
}

// reduce partials + bias + sigmoid -> g_h; optionally save hinit/hfinal
__global__ void k_hred(const float* __restrict__ b, int save) {
    int j = blockIdx.x * 256 + threadIdx.x;
    float s = b[j];
#pragma unroll 8
    for (int r = 0; r < RCH; r++) s += g_part[r * HID + j];
    float h = sigm(s);
    g_h[j] = h;
    if (save == 1) g_hA[j] = h;        // hinit_0 (q for sample 1)
    else if (save == 2) g_hB[j] = h;   // hfinal_0 (s for sample 1)
}

// v = sigmoid(a + W h): one warp per row, 16 rows per 512-thread block, uint4 loads.
__global__ void k_gemv(const float* __restrict__ a) {
    __shared__ float sh[HID];
    for (int k = threadIdx.x; k < HID; k += blockDim.x) sh[k] = g_h[k];
    __syncthreads();
    int warp = threadIdx.x >> 5, lane = threadIdx.x & 31;
    int row = blockIdx.x * 16 + warp;
    const uint4* Wr = (const uint4*)(g_Wh + (size_t)row * HID);   // 8 halves/load
    float acc = 0.f;
#pragma unroll 8
    for (int i = lane; i < HID / 8; i += 32) {
        uint4 wv = Wr[i];
        float2 f0 = __half22float2(*reinterpret_cast<__half2*>(&wv.x));
        float2 f1 = __half22float2(*reinterpret_cast<__half2*>(&wv.y));
        float2 f2 = __half22float2(*reinterpret_cast<__half2*>(&wv.z));
        float2 f3 = __half22float2(*reinterpret_cast<__half2*>(&wv.w));
        float4 h0 = *(const float4*)&sh[8 * i];
        float4 h1 = *(const float4*)&sh[8 * i + 4];
        acc += f0.x * h0.x + f0.y * h0.y + f1.x * h0.z + f1.y * h0.w;
        acc += f2.x * h1.x + f2.y * h1.y + f3.x * h1.z + f3.y * h1.w;
    }
#pragma unroll
    for (int o = 16; o; o >>= 1) acc += __shfl_down_sync(0xffffffffu, acc, o);
    if (lane == 0) g_vA[row] = sigm(a[row] + acc);
}

// ---------------- cheap phase: samples 1..15, rank-2 W, register-resident ----------
// Carry state (q,s,r) lives in registers (28 floats/thread). Outer loops are
// #pragma unroll 1 to keep the body small (single copy -> no I$ thrash at
// grid=1, no register spills under the 64-reg cap). p streams from L1/L2-hot
// gmem instead of a register array.

__device__ __forceinline__ float2 blockdot2(float a, float b) {
    __shared__ float ra[32], rb[32], bc[2];
#pragma unroll
    for (int o = 16; o; o >>= 1) {
        a += __shfl_down_sync(0xffffffffu, a, o);
        b += __shfl_down_sync(0xffffffffu, b, o);
    }
    int w = threadIdx.x >> 5;
    if ((threadIdx.x & 31) == 0) { ra[w] = a; rb[w] = b; }
    __syncthreads();
    if (threadIdx.x < 32) {
        float x = ra[threadIdx.x], y = rb[threadIdx.x];
#pragma unroll
        for (int o = 16; o; o >>= 1) {
            x += __shfl_down_sync(0xffffffffu, x, o);
            y += __shfl_down_sync(0xffffffffu, y, o);
        }
        if (threadIdx.x == 0) { bc[0] = x; bc[1] = y; }
    }
    __syncthreads();
    float2 r; r.x = bc[0]; r.y = bc[1];
    return r;
}

__global__ void __launch_bounds__(CTH, 1) k_cheap(const float* __restrict__ inp,
                                                  float* __restrict__ out) {
    const int tid = threadIdx.x;
    float rq[HPT], rs[HPT], rqn[HPT], rsn[HPT], rr[VPT];

    // load carry state into registers (each thread only its own elements)
#pragma unroll
    for (int jj = 0; jj < HPT; jj++) {
        rq[jj] = g_hA[tid + jj * CTH];
        rs[jj] = g_hB[tid + jj * CTH];
    }
#pragma unroll
    for (int kk = 0; kk < VPT; kk++) rr[kk] = g_vA[tid + kk * CTH];

    // entry dots: d1 = inputs[0].inputs[1], d2 = vfinal_0.inputs[1]
    float2 dv;
    {
        float a1 = 0.f, a2 = 0.f;
#pragma unroll
        for (int kk = 0; kk < VPT; kk++) {
            int k = tid + kk * CTH;
            float x1v = inp[FLAT + k];
            a1 += inp[k] * x1v;
            a2 += rr[kk] * x1v;
        }
        dv = blockdot2(a1, a2);
    }

#pragma unroll 1
    for (int i = 1; i < NS; i++) {
        const float* p  = inp + (size_t)(i - 1) * FLAT;   // v_init of prev sample
        const float* pn = inp + (size_t)i * FLAT;         // v_init of this sample
        const float* xn = pn + FLAT;                      // next v_init (guarded)

#pragma unroll 1
        for (int t = 1; t <= KST; t++) {
            // ---- h phase: h = sigm(LR*(q*(1+d1) - s*(1+d2))); dots q.h, s.h
            float c1 = 1.f + dv.x, c2 = 1.f + dv.y;
            float a3 = 0.f, a4 = 0.f;
#pragma unroll
            for (int jj = 0; jj < HPT; jj++) {
                float h = sigm(LRf * (rq[jj] * c1 - rs[jj] * c2));
                if (t == 1) rqn[jj] = h;
                if (t == KST) rsn[jj] = h;
                a3 += rq[jj] * h;
                a4 += rs[jj] * h;
            }
            float2 dh = blockdot2(a3, a4);

            // ---- v phase: v = sigm(LR*(p*(1+d3) - r*(1+d4))); next-step dots
            float c3 = 1.f + dh.x, c4 = 1.f + dh.y;
            float a1 = 0.f, a2 = 0.f;
            if (t < KST) {
#pragma unroll
                for (int kk = 0; kk < VPT; kk++) {
                    int k = tid + kk * CTH;
                    float pk = p[k];
                    float v = sigm(LRf * (pk * c3 - rr[kk] * c4));
                    a1 += pk * v;          // p.v for next step
                    a2 += rr[kk] * v;      // r.v for next step
                }
            } else if (i < NS - 1) {
#pragma unroll
                for (int kk = 0; kk < VPT; kk++) {
                    int k = tid + kk * CTH;
                    float v = sigm(LRf * (p[k] * c3 - rr[kk] * c4));
                    rr[kk] = v;                        // vfinal_i -> r (register)
                    float xnk = xn[k];
                    a1 += pn[k] * xnk;                 // inputs[i].inputs[i+1]
                    a2 += v * xnk;                     // vfinal_i.inputs[i+1]
                }
            } else {
#pragma unroll
                for (int kk = 0; kk < VPT; kk++) {
                    int k = tid + kk * CTH;
                    float v = sigm(LRf * (p[k] * c3 - rr[kk] * c4));
                    out[k] = v;                        // final reconstruction
                }
            }
            dv = blockdot2(a1, a2);
        }
        // carry rotate: pure register copies
#pragma unroll
        for (int jj = 0; jj < HPT; jj++) { rq[jj] = rqn[jj]; rs[jj] = rsn[jj]; }
    }
}

// ---------------- launch ----------------

extern "C" void kernel_launch(void* const* d_in, const int* in_sizes, int n_in,
                              void* d_out, int out_size) {
    const float* inp = (const float*)d_in[0];  // (16, 64, 64, 3) = 16 x 12288
    const float* W   = (const float*)d_in[1];  // (12288, 4096)
    const float* a   = (const float*)d_in[2];  // (12288, 1)
    const float* b   = (const float*)d_in[3];  // (4096, 1)
    float* out = (float*)d_out;                // (12288, 1)

    float* vA = 0;
    cudaGetSymbolAddress((void**)&vA, g_vA);

    dim3 gT(HID / 512, RCH);
    for (int s = 0; s < KST; s++) {
        if (s == 0) k_gemvT_conv<<<gT, 256>>>(W, inp);   // fused fp16 conversion
        else        k_gemvT<<<gT, 256>>>(vA);
        k_hred<<<HID / 256, 256>>>(b, (s == 0) ? 1 : ((s == KST - 1) ? 2 : 0));
        k_gemv<<<FLAT / 16, 512>>>(a);
    }
    k_cheap<<<1, CTH>>>(inp, out);
}

// round 14
// speedup vs baseline: 1.9635x; 1.4002x over previous
#include <cuda_runtime.h>
#include <cuda_fp16.h>

#define FLAT 12288
#define HID  4096
#define NS   16
#define KST  4
#define LRf  0.01f
#define LRh  0.005f      // 0.5 * LR, folded into tanh-form sigmoid
#define RCH  96          // row chunks for W^T v partials (128 rows each)
#define ROWS_PER_CH 128
#define CTH  1024        // cheap-phase threads (single block)
#define VPT  (FLAT / CTH)   // 12 v-elements per thread
#define HPT  (HID / CTH)    // 4 h-elements per thread

// ---------------- device scratch (static, no runtime allocation) ----------------
__device__ __half g_Wh[(size_t)FLAT * HID];  // fp16 copy of W (96 MB)
__device__ float g_part[RCH * HID];   // gemvT partial column sums
__device__ float g_h[HID];            // dense-phase working h
__device__ float g_hA[HID];           // hinit_0 (q)
__device__ float g_hB[HID];           // hfinal_0 (s)
__device__ float g_vA[FLAT];          // vfinal_0 (r)

__device__ __forceinline__ float sigm(float x) { return 1.f / (1.f + __expf(-x)); }
// fast sigmoid: sigma(2y) = 0.5 + 0.5*tanh(y); caller pre-halves the logit
__device__ __forceinline__ float tanha(float x) {
    float y;
    asm("tanh.approx.f32 %0, %1;" : "=f"(y) : "f"(x));
    return y;
}

// ---------------- dense phase: sample 0 (proven R10/R13 config, untouched) ----------

// Pass 1 of gemvT, fused with W->fp16 conversion: reads fp32 W (200MB) once,
// emits fp16 copy (100MB) and partial column sums. 128-row chunks, grid (8,96).
__global__ void k_gemvT_conv(const float* __restrict__ W, const float* __restrict__ v) {
    __shared__ float sv[ROWS_PER_CH];
    int r0 = blockIdx.y * ROWS_PER_CH;
    if (threadIdx.x < ROWS_PER_CH) sv[threadIdx.x] = v[r0 + threadIdx.x];
    __syncthreads();
    int col2 = blockIdx.x * 256 + threadIdx.x;      // float2/half2 column index
    const float2* Wp = (const float2*)W + (size_t)r0 * (HID / 2) + col2;
    __half2* Whp = (__half2*)g_Wh + (size_t)r0 * (HID / 2) + col2;
    float ax = 0.f, ay = 0.f;
#pragma unroll 8
    for (int r = 0; r < ROWS_PER_CH; r++) {
        float2 w = Wp[(size_t)r * (HID / 2)];
        Whp[(size_t)r * (HID / 2)] = __floats2half2_rn(w.x, w.y);
        float s = sv[r];
        ax += w.x * s;
        ay += w.y * s;
    }
    float2 o; o.x = ax; o.y = ay;
    ((float2*)g_part)[blockIdx.y * (HID / 2) + col2] = o;
}

// Passes 2..4: fp16 W. 256 threads x half2 (512 cols per block), grid (8, 96).
__global__ void k_gemvT(const float* __restrict__ v) {
    __shared__ float sv[ROWS_PER_CH];
    int r0 = blockIdx.y * ROWS_PER_CH;
    if (threadIdx.x < ROWS_PER_CH) sv[threadIdx.x] = v[r0 + threadIdx.x];
    __syncthreads();
    int col2 = blockIdx.x * 256 + threadIdx.x;      // half2 column index
    const __half2* Wp = (const __half2*)g_Wh + (size_t)r0 * (HID / 2) + col2;
    float ax = 0.f, ay = 0.f;
#pragma unroll 8
    for (int r = 0; r < ROWS_PER_CH; r++) {
        float2 w = __half22float2(Wp[(size_t)r * (HID / 2)]);
        float s = sv[r];
        ax += w.x * s;
        ay += w.y * s;
    }
    float2 o; o.x = ax; o.y = ay;
    ((float2*)g_part)[blockIdx.y * (HID / 2) + col2] = o;
}

// reduce partials + bias + sigmoid -> g_h; optionally save hinit/hfinal
__global__ void k_hred(const float* __restrict__ b, int save) {
    int j = blockIdx.x * 256 + threadIdx.x;
    float s = b[j];
#pragma unroll 8
    for (int r = 0; r < RCH; r++) s += g_part[r * HID + j];
    float h = sigm(s);
    g_h[j] = h;
    if (save == 1) g_hA[j] = h;        // hinit_0 (q for sample 1)
    else if (save == 2) g_hB[j] = h;   // hfinal_0 (s for sample 1)
}

// v = sigmoid(a + W h): one warp per row, 16 rows per 512-thread block, uint4 loads.
__global__ void k_gemv(const float* __restrict__ a) {
    __shared__ float sh[HID];
    for (int k = threadIdx.x; k < HID; k += blockDim.x) sh[k] = g_h[k];
    __syncthreads();
    int warp = threadIdx.x >> 5, lane = threadIdx.x & 31;
    int row = blockIdx.x * 16 + warp;
    const uint4* Wr = (const uint4*)(g_Wh + (size_t)row * HID);   // 8 halves/load
    float acc = 0.f;
#pragma unroll 8
    for (int i = lane; i < HID / 8; i += 32) {
        uint4 wv = Wr[i];
        float2 f0 = __half22float2(*reinterpret_cast<__half2*>(&wv.x));
        float2 f1 = __half22float2(*reinterpret_cast<__half2*>(&wv.y));
        float2 f2 = __half22float2(*reinterpret_cast<__half2*>(&wv.z));
        float2 f3 = __half22float2(*reinterpret_cast<__half2*>(&wv.w));
        float4 h0 = *(const float4*)&sh[8 * i];
        float4 h1 = *(const float4*)&sh[8 * i + 4];
        acc += f0.x * h0.x + f0.y * h0.y + f1.x * h0.z + f1.y * h0.w;
        acc += f2.x * h1.x + f2.y * h1.y + f3.x * h1.z + f3.y * h1.w;
    }
#pragma unroll
    for (int o = 16; o; o >>= 1) acc += __shfl_down_sync(0xffffffffu, acc, o);
    if (lane == 0) g_vA[row] = sigm(a[row] + acc);
}

// ---------------- cheap phase: samples 1..15, rank-2 W, register-resident ----------
// Issue/MUFU-bound on one SM -> minimize instructions: sigmoid via single
// tanh.approx (0.5*LR folded into the phase constants). Final out store uses
// the exact expf sigmoid so the output carries no approximation error.

__device__ __forceinline__ float2 blockdot2(float a, float b) {
    __shared__ float ra[32], rb[32], bc[2];
#pragma unroll
    for (int o = 16; o; o >>= 1) {
        a += __shfl_down_sync(0xffffffffu, a, o);
        b += __shfl_down_sync(0xffffffffu, b, o);
    }
    int w = threadIdx.x >> 5;
    if ((threadIdx.x & 31) == 0) { ra[w] = a; rb[w] = b; }
    __syncthreads();
    if (threadIdx.x < 32) {
        float x = ra[threadIdx.x], y = rb[threadIdx.x];
#pragma unroll
        for (int o = 16; o; o >>= 1) {
            x += __shfl_down_sync(0xffffffffu, x, o);
            y += __shfl_down_sync(0xffffffffu, y, o);
        }
        if (threadIdx.x == 0) { bc[0] = x; bc[1] = y; }
    }
    __syncthreads();
    float2 r; r.x = bc[0]; r.y = bc[1];
    return r;
}

__global__ void __launch_bounds__(CTH, 1) k_cheap(const float* __restrict__ inp,
                                                  float* __restrict__ out) {
    const int tid = threadIdx.x;
    float rq[HPT], rs[HPT], rqn[HPT], rsn[HPT], rr[VPT];

    // load carry state into registers (each thread only its own elements)
#pragma unroll
    for (int jj = 0; jj < HPT; jj++) {
        rq[jj] = g_hA[tid + jj * CTH];
        rs[jj] = g_hB[tid + jj * CTH];
    }
#pragma unroll
    for (int kk = 0; kk < VPT; kk++) rr[kk] = g_vA[tid + kk * CTH];

    // entry dots: d1 = inputs[0].inputs[1], d2 = vfinal_0.inputs[1]
    float2 dv;
    {
        float a1 = 0.f, a2 = 0.f;
#pragma unroll
        for (int kk = 0; kk < VPT; kk++) {
            int k = tid + kk * CTH;
            float x1v = inp[FLAT + k];
            a1 += inp[k] * x1v;
            a2 += rr[kk] * x1v;
        }
        dv = blockdot2(a1, a2);
    }

#pragma unroll 1
    for (int i = 1; i < NS; i++) {
        const float* p  = inp + (size_t)(i - 1) * FLAT;   // v_init of prev sample
        const float* pn = inp + (size_t)i * FLAT;         // v_init of this sample
        const float* xn = pn + FLAT;                      // next v_init (guarded)

#pragma unroll 1
        for (int t = 1; t <= KST; t++) {
            // ---- h phase: h = sigm(LR*(q*(1+d1) - s*(1+d2)))
            //      tanh form: h = 0.5 + 0.5*tanh(q*c1 - s*c2), c = 0.5*LR*(1+d)
            float c1 = LRh * (1.f + dv.x), c2 = LRh * (1.f + dv.y);
            float a3 = 0.f, a4 = 0.f;
#pragma unroll
            for (int jj = 0; jj < HPT; jj++) {
                float th = tanha(rq[jj] * c1 - rs[jj] * c2);
                float h = fmaf(0.5f, th, 0.5f);
                if (t == 1) rqn[jj] = h;
                if (t == KST) rsn[jj] = h;
                a3 += rq[jj] * h;
                a4 += rs[jj] * h;
            }
            float2 dh = blockdot2(a3, a4);

            // ---- v phase: v = sigm(LR*(p*(1+d3) - r*(1+d4)))
            float c3 = LRh * (1.f + dh.x), c4 = LRh * (1.f + dh.y);
            float a1 = 0.f, a2 = 0.f;
            if (t < KST) {
#pragma unroll
                for (int kk = 0; kk < VPT; kk++) {
                    int k = tid + kk * CTH;
                    float pk = p[k];
                    float v = fmaf(0.5f, tanha(pk * c3 - rr[kk] * c4), 0.5f);
                    a1 += pk * v;          // p.v for next step
                    a2 += rr[kk] * v;      // r.v for next step
                }
            } else if (i < NS - 1) {
#pragma unroll
                for (int kk = 0; kk < VPT; kk++) {
                    int k = tid + kk * CTH;
                    float v = fmaf(0.5f, tanha(p[k] * c3 - rr[kk] * c4), 0.5f);
                    rr[kk] = v;                        // vfinal_i -> r (register)
                    float xnk = xn[k];
                    a1 += pn[k] * xnk;                 // inputs[i].inputs[i+1]
                    a2 += v * xnk;                     // vfinal_i.inputs[i+1]
                }
            } else {
                // final reconstruction: exact sigmoid (no approx error in out)
                float e3 = LRf * (1.f + dh.x), e4 = LRf * (1.f + dh.y);
#pragma unroll
                for (int kk = 0; kk < VPT; kk++) {
                    int k = tid + kk * CTH;
                    float v = sigm(p[k] * e3 - rr[kk] * e4);
                    out[k] = v;
                }
            }
            dv = blockdot2(a1, a2);
        }
        // carry rotate: pure register copies
#pragma unroll
        for (int jj = 0; jj < HPT; jj++) { rq[jj] = rqn[jj]; rs[jj] = rsn[jj]; }
    }
}

// ---------------- launch ----------------

extern "C" void kernel_launch(void* const* d_in, const int* in_sizes, int n_in,
                              void* d_out, int out_size) {
    const float* inp = (const float*)d_in[0];  // (16, 64, 64, 3) = 16 x 12288
    const float* W   = (const float*)d_in[1];  // (12288, 4096)
    const float* a   = (const float*)d_in[2];  // (12288, 1)
    const float* b   = (const float*)d_in[3];  // (4096, 1)
    float* out = (float*)d_out;                // (12288, 1)

    float* vA = 0;
    cudaGetSymbolAddress((void**)&vA, g_vA);

    dim3 gT(HID / 512, RCH);
    for (int s = 0; s < KST; s++) {
        if (s == 0) k_gemvT_conv<<<gT, 256>>>(W, inp);   // fused fp16 conversion
        else        k_gemvT<<<gT, 256>>>(vA);
        k_hred<<<HID / 256, 256>>>(b, (s == 0) ? 1 : ((s == KST - 1) ? 2 : 0));
        k_gemv<<<FLAT / 16, 512>>>(a);
    }
    k_cheap<<<1, CTH>>>(inp, out);
}